// round 11
// baseline (speedup 1.0000x reference)
#include <cuda_runtime.h>
#include <cuda_bf16.h>
#include <cstdint>

// ---------------------------------------------------------------- constants
#define NB 4
#define LSEQ 2048
#define EDIM 1024
#define HID 1024
#define HEADS 16
#define DH 64
#define MROWS (NB*LSEQ)          // 8192
#define NHTOT (NB*HEADS)         // 64

#define BM 128
#define BN 128
#define BK 16
#define LDS 20                   // gemm smem row stride in words (conflict-free, 16B-aligned chunks)
#define STAGES 4
#define CHUNK_W (BM*LDS)         // 2560 words per operand per stage
#define CHUNK_B (CHUNK_W*4)      // 10240 bytes
#define GEMM_SMEM (2*STAGES*CHUNK_B)   // 81920 bytes
#define SQS 36                   // scores bf16 smem stride (conflict-free)

// ---------------------------------------------------------------- scratch
__device__ float g_Xr [(size_t)MROWS*EDIM];  // rna(X)
__device__ float g_WT [3u*EDIM*HID];         // rna(Wq^T,Wk^T,Wv^T) [N,K]
__device__ float g_WoT[(size_t)HID*HID];     // rna(Wo^T)           [N,K]
__device__ float g_Qp [(size_t)NHTOT*LSEQ*DH];
__device__ float g_Kp [(size_t)NHTOT*LSEQ*DH];
__device__ float g_V  [(size_t)MROWS*HID];
__device__ float g_Vsr[(size_t)MROWS*HID];   // rna(diag * V)
__device__ float g_colsum[NHTOT*LSEQ];
__device__ float g_diag  [NHTOT*LSEQ];

// ---------------------------------------------------------------- helpers
__device__ __forceinline__ uint32_t f2tf32(float f) {
    uint32_t u;
    asm("cvt.rna.tf32.f32 %0, %1;" : "=r"(u) : "f"(f));
    return u;
}
__device__ __forceinline__ float f2tf32f(float f) {
    return __uint_as_float(f2tf32(f));
}
__device__ __forceinline__ uint32_t smem_u32(const void* p) {
    uint32_t a;
    asm("{ .reg .u64 t; cvta.to.shared.u64 t, %1; cvt.u32.u64 %0, t; }"
        : "=r"(a) : "l"(p));
    return a;
}

#define CP16(dst, src) \
    asm volatile("cp.async.cg.shared.global [%0], [%1], 16;" :: "r"(dst), "l"(src))
#define CP_COMMIT() asm volatile("cp.async.commit_group;" ::: "memory")
#define CP_WAIT2()  asm volatile("cp.async.wait_group 2;"  ::: "memory")

__device__ __forceinline__ void mma_tf32(float& c0, float& c1, float& c2, float& c3,
                                         uint32_t a0, uint32_t a1, uint32_t a2, uint32_t a3,
                                         uint32_t b0, uint32_t b1)
{
    asm("mma.sync.aligned.m16n8k8.row.col.f32.tf32.tf32.f32 "
        "{%0,%1,%2,%3}, {%4,%5,%6,%7}, {%8,%9}, {%0,%1,%2,%3};"
        : "+f"(c0), "+f"(c1), "+f"(c2), "+f"(c3)
        : "r"(a0), "r"(a1), "r"(a2), "r"(a3), "r"(b0), "r"(b1));
}

__device__ __forceinline__ void mma_bf16(float& c0, float& c1, float& c2, float& c3,
                                         uint32_t a0, uint32_t a1, uint32_t a2, uint32_t a3,
                                         uint32_t b0, uint32_t b1)
{
    asm("mma.sync.aligned.m16n8k16.row.col.f32.bf16.bf16.f32 "
        "{%0,%1,%2,%3}, {%4,%5,%6,%7}, {%8,%9}, {%0,%1,%2,%3};"
        : "+f"(c0), "+f"(c1), "+f"(c2), "+f"(c3)
        : "r"(a0), "r"(a1), "r"(a2), "r"(a3), "r"(b0), "r"(b1));
}

__device__ __forceinline__ uint32_t pack_bf2(float lo, float hi) {
    __nv_bfloat162 p = __float22bfloat162_rn(make_float2(lo, hi));
    return *(uint32_t*)&p;
}

// ---------------------------------------------------------------------------
// cp.async 4-stage tf32 core: C(128x128) = A[rowBase:+128,0:K] @ B[colBase:+128,0:K]^T
// Inputs must be pre-rounded to tf32 (HW truncation is then lossless).
// Both row-major, K contiguous, K mult of 16. 8 warps (2x4), warp tile 64x32.
// ---------------------------------------------------------------------------
__device__ __forceinline__ void cp_gemm(const float* __restrict__ A, int lda,
                                        const float* __restrict__ B, int ldb,
                                        int K, int rowBase, int colBase,
                                        float (&c)[4][4][4])
{
    extern __shared__ uint32_t smw[];

    const int tid  = threadIdx.x;
    const int srow = tid >> 1;          // 0..127
    const int sf   = (tid & 1) * 8;     // 0 or 8 (floats)
    const int wid  = tid >> 5, lane = tid & 31;
    const int g    = lane >> 2, t4 = lane & 3;
    const int wr   = (wid >> 2) * 64, wc = (wid & 3) * 32;

    const float* Ap = A + (size_t)(rowBase + srow) * lda + sf;
    const float* Bp = B + (size_t)(colBase + srow) * ldb + sf;
    const uint32_t sb    = smem_u32(smw);
    const uint32_t aAddr = sb + (srow * LDS + sf) * 4;
    const uint32_t bAddr = aAddr + STAGES * CHUNK_B;

    #pragma unroll
    for (int mi = 0; mi < 4; mi++)
        #pragma unroll
        for (int nj = 0; nj < 4; nj++)
            #pragma unroll
            for (int q = 0; q < 4; q++)
                c[mi][nj][q] = 0.0f;

    const int NC = K / BK;

    #define ISSUE_CHUNK(ch, st) do { \
        const float* as_ = Ap + (ch) * BK; \
        const float* bs_ = Bp + (ch) * BK; \
        const uint32_t ad = aAddr + (st) * CHUNK_B; \
        const uint32_t bd = bAddr + (st) * CHUNK_B; \
        CP16(ad,      as_);     CP16(ad + 16, as_ + 4); \
        CP16(bd,      bs_);     CP16(bd + 16, bs_ + 4); \
    } while (0)

    #pragma unroll
    for (int s = 0; s < STAGES - 1; s++) {
        ISSUE_CHUNK(s, s);
        CP_COMMIT();
    }

    for (int i = 0; i < NC; i++) {
        CP_WAIT2();
        __syncthreads();

        const int nc = i + STAGES - 1;
        if (nc < NC) ISSUE_CHUNK(nc, nc & (STAGES - 1));
        CP_COMMIT();

        const uint32_t* Aw = smw + (i & (STAGES - 1)) * CHUNK_W;
        const uint32_t* Bw = smw + STAGES * CHUNK_W + (i & (STAGES - 1)) * CHUNK_W;

        #pragma unroll
        for (int kk = 0; kk < BK; kk += 8) {
            uint32_t a[4][4], b[4][2];
            #pragma unroll
            for (int mi = 0; mi < 4; mi++) {
                const int rb = (wr + mi * 16 + g) * LDS + kk + t4;
                a[mi][0] = Aw[rb];
                a[mi][1] = Aw[rb + 8 * LDS];
                a[mi][2] = Aw[rb + 4];
                a[mi][3] = Aw[rb + 8 * LDS + 4];
            }
            #pragma unroll
            for (int nj = 0; nj < 4; nj++) {
                const int cb = (wc + nj * 8 + g) * LDS + kk + t4;
                b[nj][0] = Bw[cb];
                b[nj][1] = Bw[cb + 4];
            }
            #pragma unroll
            for (int mi = 0; mi < 4; mi++)
                #pragma unroll
                for (int nj = 0; nj < 4; nj++)
                    mma_tf32(c[mi][nj][0], c[mi][nj][1], c[mi][nj][2], c[mi][nj][3],
                             a[mi][0], a[mi][1], a[mi][2], a[mi][3],
                             b[nj][0], b[nj][1]);
        }
    }
    #undef ISSUE_CHUNK
}

// ---------------------------------------------------------------- prep kernels
// transpose 1024x1024 weights into [N,K], rounded to tf32
__global__ __launch_bounds__(256)
void transpose_kernel(const float* __restrict__ Wq, const float* __restrict__ Wk,
                      const float* __restrict__ Wv, const float* __restrict__ Wo)
{
    __shared__ float t[32][33];
    const int z = blockIdx.z;
    const float* src = (z == 0) ? Wq : (z == 1) ? Wk : (z == 2) ? Wv : Wo;
    float* dst = (z < 3) ? (g_WT + (size_t)z * EDIM * HID) : g_WoT;
    const int tx = threadIdx.x & 31, ty = threadIdx.x >> 5;
    const int x = blockIdx.x * 32 + tx;
    const int y0 = blockIdx.y * 32 + ty;
    #pragma unroll
    for (int i = 0; i < 32; i += 8)
        t[ty + i][tx] = src[(size_t)(y0 + i) * 1024 + x];
    __syncthreads();
    const int x2 = blockIdx.y * 32 + tx;
    const int y2 = blockIdx.x * 32 + ty;
    #pragma unroll
    for (int i = 0; i < 32; i += 8)
        dst[(size_t)(y2 + i) * 1024 + x2] = f2tf32f(t[tx][ty + i]);
}

// round X to tf32 into g_Xr
__global__ __launch_bounds__(256)
void round_x(const float* __restrict__ X)
{
    const int idx4 = blockIdx.x * blockDim.x + threadIdx.x;
    if (idx4 >= (MROWS * EDIM) / 4) return;
    float4 v = ((const float4*)X)[idx4];
    v.x = f2tf32f(v.x); v.y = f2tf32f(v.y);
    v.z = f2tf32f(v.z); v.w = f2tf32f(v.w);
    ((float4*)g_Xr)[idx4] = v;
}

// QKV projections: z=0 Q (permuted), z=1 K (permuted), z=2 V (natural)
__global__ __launch_bounds__(256, 2)
void qkv_mma(const float* __restrict__ bq, const float* __restrict__ bk,
             const float* __restrict__ bv)
{
    const int z = blockIdx.z;
    const float* W    = g_WT + (size_t)z * EDIM * HID;
    const float* bias = (z == 0) ? bq : (z == 1) ? bk : bv;
    const int rowBase = blockIdx.y * BM;
    const int colBase = blockIdx.x * BN;

    float c[4][4][4];
    cp_gemm(g_Xr, EDIM, W, EDIM, EDIM, rowBase, colBase, c);

    const int tid = threadIdx.x, wid = tid >> 5, lane = tid & 31;
    const int g = lane >> 2, t4 = lane & 3;
    const int wr = (wid >> 2) * 64, wc = (wid & 3) * 32;
    float* dq = (z == 0) ? g_Qp : g_Kp;

    #pragma unroll
    for (int mi = 0; mi < 4; mi++) {
        #pragma unroll
        for (int nj = 0; nj < 4; nj++) {
            const int cc = colBase + wc + nj * 8 + t4 * 2;
            const float bx = bias[cc], by = bias[cc + 1];
            #pragma unroll
            for (int half = 0; half < 2; half++) {
                const int r = rowBase + wr + mi * 16 + g + half * 8;
                float2 v;
                v.x = c[mi][nj][half * 2 + 0] + bx;
                v.y = c[mi][nj][half * 2 + 1] + by;
                if (z == 2) {
                    *(float2*)&g_V[(size_t)r * HID + cc] = v;
                } else {
                    const int n = r >> 11, lrow = r & 2047, h = lrow >> 7;
                    const int a = ((lrow & 127) << 4) + (cc >> 6);
                    const int x = cc & 63;
                    *(float2*)&dq[(((size_t)(n * HEADS + h) * LSEQ) + a) * DH + x] = v;
                }
            }
        }
    }
}

// ---------------------------------------------------------------------------
// scores: CTA = (b-strip of 128, nh). K-strip resident (bf16, frags in regs),
// stream 16 Q tiles, colsum[b] = sum_a exp(S[a,b]/HID), direct store.
// ---------------------------------------------------------------------------
__global__ __launch_bounds__(256, 2)
void scores_mma()
{
    __shared__ uint32_t Ks[128 * SQS];
    __shared__ uint32_t Qs[128 * SQS];
    __shared__ float red[128];

    const int nh      = blockIdx.y;
    const int colBase = blockIdx.x * 128;
    const float* Qh = g_Qp + (size_t)nh * LSEQ * DH;
    const float* Kh = g_Kp + (size_t)nh * LSEQ * DH;

    const int tid = threadIdx.x;
    const int wid = tid >> 5, lane = tid & 31;
    const int g = lane >> 2, t4 = lane & 3;
    const int wr = (wid >> 2) * 64;
    const int wc = (wid & 3) * 32;

    const int srow = tid >> 1;
    const int sf4  = (tid & 1) * 8;

    {
        const float4* src = (const float4*)(Kh + (size_t)(colBase + srow) * DH) + sf4;
        uint32_t* dst = &Ks[srow * SQS + sf4 * 2];
        #pragma unroll
        for (int i = 0; i < 8; i++) {
            float4 v = src[i];
            dst[2*i]   = pack_bf2(v.x, v.y);
            dst[2*i+1] = pack_bf2(v.z, v.w);
        }
    }
    if (tid < 128) red[tid] = 0.0f;
    __syncthreads();

    uint32_t bf[4][4][2];
    #pragma unroll
    for (int nj = 0; nj < 4; nj++) {
        const int crow = (wc + nj * 8 + g) * SQS;
        #pragma unroll
        for (int ks = 0; ks < 4; ks++) {
            bf[nj][ks][0] = Ks[crow + ks * 8 + t4];
            bf[nj][ks][1] = Ks[crow + ks * 8 + t4 + 4];
        }
    }

    const float inv = 1.0f / (float)HID;
    float cs[4][2];
    #pragma unroll
    for (int nj = 0; nj < 4; nj++) { cs[nj][0] = 0.0f; cs[nj][1] = 0.0f; }

    for (int it = 0; it < 16; it++) {
        float4 pf[8];
        const float4* src = (const float4*)(Qh + (size_t)(it * 128 + srow) * DH) + sf4;
        #pragma unroll
        for (int i = 0; i < 8; i++) pf[i] = src[i];

        __syncthreads();
        {
            uint32_t* dst = &Qs[srow * SQS + sf4 * 2];
            #pragma unroll
            for (int i = 0; i < 8; i++) {
                dst[2*i]   = pack_bf2(pf[i].x, pf[i].y);
                dst[2*i+1] = pack_bf2(pf[i].z, pf[i].w);
            }
        }
        __syncthreads();

        #pragma unroll
        for (int mi = 0; mi < 4; mi++) {
            const int ar = (wr + mi * 16 + g) * SQS;
            uint32_t af[4][4];
            #pragma unroll
            for (int ks = 0; ks < 4; ks++) {
                af[ks][0] = Qs[ar + ks * 8 + t4];
                af[ks][1] = Qs[ar + 8 * SQS + ks * 8 + t4];
                af[ks][2] = Qs[ar + ks * 8 + t4 + 4];
                af[ks][3] = Qs[ar + 8 * SQS + ks * 8 + t4 + 4];
            }
            #pragma unroll
            for (int nj = 0; nj < 4; nj++) {
                float c0 = 0.f, c1 = 0.f, c2 = 0.f, c3 = 0.f;
                #pragma unroll
                for (int ks = 0; ks < 4; ks++)
                    mma_bf16(c0, c1, c2, c3,
                             af[ks][0], af[ks][1], af[ks][2], af[ks][3],
                             bf[nj][ks][0], bf[nj][ks][1]);
                cs[nj][0] += __expf(c0 * inv) + __expf(c2 * inv);
                cs[nj][1] += __expf(c1 * inv) + __expf(c3 * inv);
            }
        }
    }

    #pragma unroll
    for (int nj = 0; nj < 4; nj++)
        #pragma unroll
        for (int p = 0; p < 2; p++) {
            float v = cs[nj][p];
            v += __shfl_xor_sync(0xffffffffu, v, 4);
            v += __shfl_xor_sync(0xffffffffu, v, 8);
            v += __shfl_xor_sync(0xffffffffu, v, 16);
            cs[nj][p] = v;
        }
    if (g == 0) {
        #pragma unroll
        for (int nj = 0; nj < 4; nj++) {
            atomicAdd(&red[wc + nj * 8 + t4 * 2],     cs[nj][0]);
            atomicAdd(&red[wc + nj * 8 + t4 * 2 + 1], cs[nj][1]);
        }
    }
    __syncthreads();
    if (tid < 128)
        g_colsum[nh * LSEQ + colBase + tid] = red[tid];
}

// diag[b] = exp(dot(Q[b],K[b])/HID) / colsum[b]  (exact fp32 diagonal)
__global__ void diag_kernel()
{
    const int idx = blockIdx.x * blockDim.x + threadIdx.x;
    if (idx >= NHTOT * LSEQ) return;
    const float4* q = (const float4*)(g_Qp + (size_t)idx * DH);
    const float4* k = (const float4*)(g_Kp + (size_t)idx * DH);
    float s = 0.0f;
    #pragma unroll
    for (int i = 0; i < DH / 4; i++) {
        float4 a = q[i], b = k[i];
        s += a.x * b.x + a.y * b.y + a.z * b.z + a.w * b.w;
    }
    s *= 1.0f / (float)HID;
    g_diag[idx] = __expf(s) / g_colsum[idx];
}

// Vsr = rna(diag * V)  (natural layout)
__global__ __launch_bounds__(256)
void scalev_round()
{
    const int idx4 = blockIdx.x * blockDim.x + threadIdx.x;
    if (idx4 >= (MROWS * HID) / 4) return;
    const int idx  = idx4 * 4;
    const int r    = idx >> 10;
    const int cc   = idx & 1023;
    const int n    = r >> 11;
    const int lrow = r & 2047;
    const int h    = lrow >> 7;
    const int a    = ((lrow & 127) << 4) + (cc >> 6);
    const float d  = g_diag[((n * HEADS + h) << 11) + a];
    float4 v = *(const float4*)&g_V[idx];
    v.x = f2tf32f(v.x * d); v.y = f2tf32f(v.y * d);
    v.z = f2tf32f(v.z * d); v.w = f2tf32f(v.w * d);
    *(float4*)&g_Vsr[idx] = v;
}

// out = Vsr @ Wo + bo
__global__ __launch_bounds__(256, 2)
void out_mma(const float* __restrict__ bo, float* __restrict__ out)
{
    const int rowBase = blockIdx.y * BM;
    const int colBase = blockIdx.x * BN;

    float c[4][4][4];
    cp_gemm(g_Vsr, HID, g_WoT, HID, HID, rowBase, colBase, c);

    const int tid = threadIdx.x, wid = tid >> 5, lane = tid & 31;
    const int g = lane >> 2, t4 = lane & 3;
    const int wr = (wid >> 2) * 64, wc = (wid & 3) * 32;

    #pragma unroll
    for (int mi = 0; mi < 4; mi++) {
        #pragma unroll
        for (int nj = 0; nj < 4; nj++) {
            const int cc = colBase + wc + nj * 8 + t4 * 2;
            const float bx = bo[cc], by = bo[cc + 1];
            #pragma unroll
            for (int half = 0; half < 2; half++) {
                const int r = rowBase + wr + mi * 16 + g + half * 8;
                float2 v;
                v.x = c[mi][nj][half * 2 + 0] + bx;
                v.y = c[mi][nj][half * 2 + 1] + by;
                *(float2*)&out[(size_t)r * HID + cc] = v;
            }
        }
    }
}

// ---------------------------------------------------------------- launch
extern "C" void kernel_launch(void* const* d_in, const int* in_sizes, int n_in,
                              void* d_out, int out_size)
{
    const float* X  = (const float*)d_in[0];
    const float* Wq = (const float*)d_in[1];
    const float* bq = (const float*)d_in[2];
    const float* Wk = (const float*)d_in[3];
    const float* bk = (const float*)d_in[4];
    const float* Wv = (const float*)d_in[5];
    const float* bv = (const float*)d_in[6];
    const float* Wo = (const float*)d_in[7];
    const float* bo = (const float*)d_in[8];
    float* out = (float*)d_out;

    cudaFuncSetAttribute(qkv_mma, cudaFuncAttributeMaxDynamicSharedMemorySize, GEMM_SMEM);
    cudaFuncSetAttribute(out_mma, cudaFuncAttributeMaxDynamicSharedMemorySize, GEMM_SMEM);

    // 1. prep: transpose+round weights, round X
    {
        dim3 grid(32, 32, 4);
        transpose_kernel<<<grid, 256>>>(Wq, Wk, Wv, Wo);
    }
    round_x<<<(MROWS * EDIM / 4 + 255) / 256, 256>>>(X);
    // 2. QKV projections (tf32 mma.sync, cp.async pipeline)
    {
        dim3 grid(HID / BN, MROWS / BM, 3);
        qkv_mma<<<grid, 256, GEMM_SMEM>>>(bq, bk, bv);
    }
    // 3. scores: K-resident bf16, writes colsum directly
    {
        dim3 grid(LSEQ / 128, NHTOT);
        scores_mma<<<grid, 256>>>();
    }
    // 4. softmax diagonal (exact fp32 dot)
    diag_kernel<<<(NHTOT * LSEQ + 255) / 256, 256>>>();
    // 5. Vsr = rna(diag*V)
    scalev_round<<<(MROWS * HID / 4 + 255) / 256, 256>>>();
    // 6. output projection (cp.async pipeline)
    {
        dim3 grid(HID / BN, MROWS / BM, 1);
        out_mma<<<grid, 256, GEMM_SMEM>>>(bo, out);
    }
}

// round 14
// speedup vs baseline: 1.3919x; 1.3919x over previous
#include <cuda_runtime.h>
#include <cuda_bf16.h>
#include <cstdint>

// ---------------------------------------------------------------- constants
#define NB 4
#define LSEQ 2048
#define EDIM 1024
#define HID 1024
#define HEADS 16
#define DH 64
#define MROWS (NB*LSEQ)          // 8192
#define NHTOT (NB*HEADS)         // 64

#define BM 128
#define BN 128
#define BK 16
#define LDS 20                   // tf32 gemm smem row stride in words (conflict-free)
#define SQS 36                   // scores bf16 smem stride in half2 words (conflict-free)

// ---------------------------------------------------------------- scratch
__device__ float g_WT [3u*EDIM*HID];         // Wq^T, Wk^T, Wv^T  [N,K]
__device__ float g_WoT[(size_t)HID*HID];     // Wo^T              [N,K]
__device__ float g_Qp [(size_t)NHTOT*LSEQ*DH];
__device__ float g_Kp [(size_t)NHTOT*LSEQ*DH];
__device__ float g_V  [(size_t)MROWS*HID];
__device__ float g_diag  [NHTOT*LSEQ];

// ---------------------------------------------------------------- helpers
__device__ __forceinline__ uint32_t f2tf32(float f) {
    uint32_t u;
    asm("cvt.rna.tf32.f32 %0, %1;" : "=r"(u) : "f"(f));
    return u;
}

__device__ __forceinline__ void mma_tf32(float& c0, float& c1, float& c2, float& c3,
                                         uint32_t a0, uint32_t a1, uint32_t a2, uint32_t a3,
                                         uint32_t b0, uint32_t b1)
{
    asm("mma.sync.aligned.m16n8k8.row.col.f32.tf32.tf32.f32 "
        "{%0,%1,%2,%3}, {%4,%5,%6,%7}, {%8,%9}, {%0,%1,%2,%3};"
        : "+f"(c0), "+f"(c1), "+f"(c2), "+f"(c3)
        : "r"(a0), "r"(a1), "r"(a2), "r"(a3), "r"(b0), "r"(b1));
}

__device__ __forceinline__ void mma_bf16(float& c0, float& c1, float& c2, float& c3,
                                         uint32_t a0, uint32_t a1, uint32_t a2, uint32_t a3,
                                         uint32_t b0, uint32_t b1)
{
    asm("mma.sync.aligned.m16n8k16.row.col.f32.bf16.bf16.f32 "
        "{%0,%1,%2,%3}, {%4,%5,%6,%7}, {%8,%9}, {%0,%1,%2,%3};"
        : "+f"(c0), "+f"(c1), "+f"(c2), "+f"(c3)
        : "r"(a0), "r"(a1), "r"(a2), "r"(a3), "r"(b0), "r"(b1));
}

__device__ __forceinline__ uint32_t pack_bf2(float lo, float hi) {
    __nv_bfloat162 p = __float22bfloat162_rn(make_float2(lo, hi));
    return *(uint32_t*)&p;
}

// ---------------------------------------------------------------------------
// tf32 core: C(128x128) = A[rowBase:+128, 0:K] @ B[colBase:+128, 0:K]^T
// Both row-major, K contiguous, K mult of 16. 8 warps (2x4), warp tile 64x32.
// SCALEA: multiply A rows by g_diag (natural-layout mapping) during staging.
// (Measured-good R6 mainloop: register prefetch + double buffer.)
// ---------------------------------------------------------------------------
template <bool SCALEA>
__device__ __forceinline__ void mma_gemm(const float* __restrict__ A, int lda,
                                         const float* __restrict__ B, int ldb,
                                         int K, int rowBase, int colBase,
                                         float (&c)[4][4][4])
{
    __shared__ uint32_t As[2][BM*LDS];
    __shared__ uint32_t Bs[2][BN*LDS];

    const int tid  = threadIdx.x;
    const int srow = tid >> 1;           // 0..127
    const int skq  = (tid & 1) * 8;      // 0 or 8
    const float* Ap = A + (size_t)(rowBase + srow) * lda + skq;
    const float* Bp = B + (size_t)(colBase + srow) * ldb + skq;

    int dbase = 0;
    if (SCALEA) {
        const int r = rowBase + srow;
        const int n = r >> 11, lrow = r & 2047, h = lrow >> 7;
        dbase = ((n * HEADS + h) << 11) + ((lrow & 127) << 4);
    }

    const int wid  = tid >> 5;
    const int lane = tid & 31;
    const int g    = lane >> 2;
    const int t4   = lane & 3;
    const int wr   = (wid >> 2) * 64;
    const int wc   = (wid & 3) * 32;

    #pragma unroll
    for (int mi = 0; mi < 4; mi++)
        #pragma unroll
        for (int nj = 0; nj < 4; nj++)
            #pragma unroll
            for (int q = 0; q < 4; q++)
                c[mi][nj][q] = 0.0f;

    const int NC = K / BK;

    // prologue: chunk 0
    {
        float4 av0 = *(const float4*)(Ap);
        float4 av1 = *(const float4*)(Ap + 4);
        if (SCALEA) {
            const float d = g_diag[dbase + (skq >> 6)];
            av0.x *= d; av0.y *= d; av0.z *= d; av0.w *= d;
            av1.x *= d; av1.y *= d; av1.z *= d; av1.w *= d;
        }
        float4 bv0 = *(const float4*)(Bp);
        float4 bv1 = *(const float4*)(Bp + 4);
        uint32_t* da = &As[0][srow * LDS + skq];
        uint32_t* db = &Bs[0][srow * LDS + skq];
        uint4 ua = make_uint4(f2tf32(av0.x), f2tf32(av0.y), f2tf32(av0.z), f2tf32(av0.w));
        uint4 ua2= make_uint4(f2tf32(av1.x), f2tf32(av1.y), f2tf32(av1.z), f2tf32(av1.w));
        uint4 ub = make_uint4(f2tf32(bv0.x), f2tf32(bv0.y), f2tf32(bv0.z), f2tf32(bv0.w));
        uint4 ub2= make_uint4(f2tf32(bv1.x), f2tf32(bv1.y), f2tf32(bv1.z), f2tf32(bv1.w));
        *(uint4*)(da)     = ua;  *(uint4*)(da + 4) = ua2;
        *(uint4*)(db)     = ub;  *(uint4*)(db + 4) = ub2;
    }
    __syncthreads();

    for (int i = 0; i < NC; i++) {
        const int cur = i & 1;

        float4 av0, av1, bv0, bv1;
        if (i + 1 < NC) {
            const int ko = (i + 1) * BK;
            av0 = *(const float4*)(Ap + ko);
            av1 = *(const float4*)(Ap + ko + 4);
            if (SCALEA) {
                const float d = g_diag[dbase + ((ko + skq) >> 6)];
                av0.x *= d; av0.y *= d; av0.z *= d; av0.w *= d;
                av1.x *= d; av1.y *= d; av1.z *= d; av1.w *= d;
            }
            bv0 = *(const float4*)(Bp + ko);
            bv1 = *(const float4*)(Bp + ko + 4);
        }

        #pragma unroll
        for (int kk = 0; kk < BK; kk += 8) {
            uint32_t a[4][4], b[4][2];
            #pragma unroll
            for (int mi = 0; mi < 4; mi++) {
                const int rb = (wr + mi * 16 + g) * LDS + kk + t4;
                a[mi][0] = As[cur][rb];
                a[mi][1] = As[cur][rb + 8 * LDS];
                a[mi][2] = As[cur][rb + 4];
                a[mi][3] = As[cur][rb + 8 * LDS + 4];
            }
            #pragma unroll
            for (int nj = 0; nj < 4; nj++) {
                const int cb = (wc + nj * 8 + g) * LDS + kk + t4;
                b[nj][0] = Bs[cur][cb];
                b[nj][1] = Bs[cur][cb + 4];
            }
            #pragma unroll
            for (int mi = 0; mi < 4; mi++)
                #pragma unroll
                for (int nj = 0; nj < 4; nj++)
                    mma_tf32(c[mi][nj][0], c[mi][nj][1], c[mi][nj][2], c[mi][nj][3],
                             a[mi][0], a[mi][1], a[mi][2], a[mi][3],
                             b[nj][0], b[nj][1]);
        }

        if (i + 1 < NC) {
            const int nxt = 1 - cur;
            uint32_t* da = &As[nxt][srow * LDS + skq];
            uint32_t* db = &Bs[nxt][srow * LDS + skq];
            uint4 ua = make_uint4(f2tf32(av0.x), f2tf32(av0.y), f2tf32(av0.z), f2tf32(av0.w));
            uint4 ua2= make_uint4(f2tf32(av1.x), f2tf32(av1.y), f2tf32(av1.z), f2tf32(av1.w));
            uint4 ub = make_uint4(f2tf32(bv0.x), f2tf32(bv0.y), f2tf32(bv0.z), f2tf32(bv0.w));
            uint4 ub2= make_uint4(f2tf32(bv1.x), f2tf32(bv1.y), f2tf32(bv1.z), f2tf32(bv1.w));
            *(uint4*)(da)     = ua;  *(uint4*)(da + 4) = ua2;
            *(uint4*)(db)     = ub;  *(uint4*)(db + 4) = ub2;
            __syncthreads();
        }
    }
}

// ---------------------------------------------------------------- kernels
// transpose 1024x1024 weights into [N,K]
__global__ __launch_bounds__(256)
void transpose_kernel(const float* __restrict__ Wq, const float* __restrict__ Wk,
                      const float* __restrict__ Wv, const float* __restrict__ Wo)
{
    __shared__ float t[32][33];
    const int z = blockIdx.z;
    const float* src = (z == 0) ? Wq : (z == 1) ? Wk : (z == 2) ? Wv : Wo;
    float* dst = (z < 3) ? (g_WT + (size_t)z * EDIM * HID) : g_WoT;
    const int tx = threadIdx.x & 31, ty = threadIdx.x >> 5;
    const int x = blockIdx.x * 32 + tx;
    const int y0 = blockIdx.y * 32 + ty;
    #pragma unroll
    for (int i = 0; i < 32; i += 8)
        t[ty + i][tx] = src[(size_t)(y0 + i) * 1024 + x];
    __syncthreads();
    const int x2 = blockIdx.y * 32 + tx;
    const int y2 = blockIdx.x * 32 + ty;
    #pragma unroll
    for (int i = 0; i < 32; i += 8)
        dst[(size_t)(y2 + i) * 1024 + x2] = t[tx][ty + i];
}

// QKV projections: z=0 Q (permuted), z=1 K (permuted), z=2 V (natural)
__global__ __launch_bounds__(256)
void qkv_mma(const float* __restrict__ X,
             const float* __restrict__ bq, const float* __restrict__ bk,
             const float* __restrict__ bv)
{
    const int z = blockIdx.z;
    const float* W    = g_WT + (size_t)z * EDIM * HID;
    const float* bias = (z == 0) ? bq : (z == 1) ? bk : bv;
    const int rowBase = blockIdx.y * BM;
    const int colBase = blockIdx.x * BN;

    float c[4][4][4];
    mma_gemm<false>(X, EDIM, W, EDIM, EDIM, rowBase, colBase, c);

    const int tid = threadIdx.x, wid = tid >> 5, lane = tid & 31;
    const int g = lane >> 2, t4 = lane & 3;
    const int wr = (wid >> 2) * 64, wc = (wid & 3) * 32;
    float* dq = (z == 0) ? g_Qp : g_Kp;

    #pragma unroll
    for (int mi = 0; mi < 4; mi++) {
        #pragma unroll
        for (int nj = 0; nj < 4; nj++) {
            const int cc = colBase + wc + nj * 8 + t4 * 2;
            const float bx = bias[cc], by = bias[cc + 1];
            #pragma unroll
            for (int half = 0; half < 2; half++) {
                const int r = rowBase + wr + mi * 16 + g + half * 8;
                float2 v;
                v.x = c[mi][nj][half * 2 + 0] + bx;
                v.y = c[mi][nj][half * 2 + 1] + by;
                if (z == 2) {
                    *(float2*)&g_V[(size_t)r * HID + cc] = v;
                } else {
                    const int n = r >> 11, lrow = r & 2047, h = lrow >> 7;
                    const int a = ((lrow & 127) << 4) + (cc >> 6);
                    const int x = cc & 63;
                    *(float2*)&dq[(((size_t)(n * HEADS + h) * LSEQ) + a) * DH + x] = v;
                }
            }
        }
    }
}

// ---------------------------------------------------------------------------
// scores: CTA = (b-strip of 128, nh). K-strip resident (bf16, frags in regs),
// stream 16 Q tiles, colsum[b] = sum_a exp(S[a,b]/HID).
// Fused epilogue: diag[b] = exp(exact_dot(Q[b],K[b])/HID) / colsum[b].
// ---------------------------------------------------------------------------
__global__ __launch_bounds__(256, 2)
void scores_mma()
{
    __shared__ uint32_t Ks[128 * SQS];
    __shared__ uint32_t Qs[128 * SQS];
    __shared__ float red[128];

    const int nh      = blockIdx.y;
    const int colBase = blockIdx.x * 128;
    const float* Qh = g_Qp + (size_t)nh * LSEQ * DH;
    const float* Kh = g_Kp + (size_t)nh * LSEQ * DH;

    const int tid = threadIdx.x;
    const int wid = tid >> 5, lane = tid & 31;
    const int g = lane >> 2, t4 = lane & 3;
    const int wr = (wid >> 2) * 64;
    const int wc = (wid & 3) * 32;

    const int srow = tid >> 1;
    const int sf4  = (tid & 1) * 8;

    {
        const float4* src = (const float4*)(Kh + (size_t)(colBase + srow) * DH) + sf4;
        uint32_t* dst = &Ks[srow * SQS + sf4 * 2];
        #pragma unroll
        for (int i = 0; i < 8; i++) {
            float4 v = src[i];
            dst[2*i]   = pack_bf2(v.x, v.y);
            dst[2*i+1] = pack_bf2(v.z, v.w);
        }
    }
    if (tid < 128) red[tid] = 0.0f;
    __syncthreads();

    uint32_t bf[4][4][2];
    #pragma unroll
    for (int nj = 0; nj < 4; nj++) {
        const int crow = (wc + nj * 8 + g) * SQS;
        #pragma unroll
        for (int ks = 0; ks < 4; ks++) {
            bf[nj][ks][0] = Ks[crow + ks * 8 + t4];
            bf[nj][ks][1] = Ks[crow + ks * 8 + t4 + 4];
        }
    }

    const float inv = 1.0f / (float)HID;
    float cs[4][2];
    #pragma unroll
    for (int nj = 0; nj < 4; nj++) { cs[nj][0] = 0.0f; cs[nj][1] = 0.0f; }

    for (int it = 0; it < 16; it++) {
        float4 pf[8];
        const float4* src = (const float4*)(Qh + (size_t)(it * 128 + srow) * DH) + sf4;
        #pragma unroll
        for (int i = 0; i < 8; i++) pf[i] = src[i];

        __syncthreads();
        {
            uint32_t* dst = &Qs[srow * SQS + sf4 * 2];
            #pragma unroll
            for (int i = 0; i < 8; i++) {
                dst[2*i]   = pack_bf2(pf[i].x, pf[i].y);
                dst[2*i+1] = pack_bf2(pf[i].z, pf[i].w);
            }
        }
        __syncthreads();

        #pragma unroll
        for (int mi = 0; mi < 4; mi++) {
            const int ar = (wr + mi * 16 + g) * SQS;
            uint32_t af[4][4];
            #pragma unroll
            for (int ks = 0; ks < 4; ks++) {
                af[ks][0] = Qs[ar + ks * 8 + t4];
                af[ks][1] = Qs[ar + 8 * SQS + ks * 8 + t4];
                af[ks][2] = Qs[ar + ks * 8 + t4 + 4];
                af[ks][3] = Qs[ar + 8 * SQS + ks * 8 + t4 + 4];
            }
            #pragma unroll
            for (int nj = 0; nj < 4; nj++) {
                float c0 = 0.f, c1 = 0.f, c2 = 0.f, c3 = 0.f;
                #pragma unroll
                for (int ks = 0; ks < 4; ks++)
                    mma_bf16(c0, c1, c2, c3,
                             af[ks][0], af[ks][1], af[ks][2], af[ks][3],
                             bf[nj][ks][0], bf[nj][ks][1]);
                cs[nj][0] += __expf(c0 * inv) + __expf(c2 * inv);
                cs[nj][1] += __expf(c1 * inv) + __expf(c3 * inv);
            }
        }
    }

    // reduce over g (lanes differing in bits 2..4), then across warps via smem
    #pragma unroll
    for (int nj = 0; nj < 4; nj++)
        #pragma unroll
        for (int p = 0; p < 2; p++) {
            float v = cs[nj][p];
            v += __shfl_xor_sync(0xffffffffu, v, 4);
            v += __shfl_xor_sync(0xffffffffu, v, 8);
            v += __shfl_xor_sync(0xffffffffu, v, 16);
            cs[nj][p] = v;
        }
    if (g == 0) {
        #pragma unroll
        for (int nj = 0; nj < 4; nj++) {
            atomicAdd(&red[wc + nj * 8 + t4 * 2],     cs[nj][0]);
            atomicAdd(&red[wc + nj * 8 + t4 * 2 + 1], cs[nj][1]);
        }
    }
    __syncthreads();

    // fused diagonal: exact fp32 dot(Q[b],K[b]) / colsum[b]  -> g_diag
    if (tid < 128) {
        const int b = colBase + tid;
        const float4* q = (const float4*)(Qh + (size_t)b * DH);
        const float4* k = (const float4*)(Kh + (size_t)b * DH);
        float s = 0.0f;
        #pragma unroll
        for (int i = 0; i < DH / 4; i++) {
            float4 a4 = q[i], b4 = k[i];
            s += a4.x * b4.x + a4.y * b4.y + a4.z * b4.z + a4.w * b4.w;
        }
        g_diag[nh * LSEQ + b] = __expf(s * inv) / red[tid];
    }
}

// out = (diag .* V) @ Wo + bo   (V scaled during A staging)
__global__ __launch_bounds__(256)
void out_mma(const float* __restrict__ bo, float* __restrict__ out)
{
    const int rowBase = blockIdx.y * BM;
    const int colBase = blockIdx.x * BN;

    float c[4][4][4];
    mma_gemm<true>(g_V, HID, g_WoT, HID, HID, rowBase, colBase, c);

    const int tid = threadIdx.x, wid = tid >> 5, lane = tid & 31;
    const int g = lane >> 2, t4 = lane & 3;
    const int wr = (wid >> 2) * 64, wc = (wid & 3) * 32;

    #pragma unroll
    for (int mi = 0; mi < 4; mi++) {
        #pragma unroll
        for (int nj = 0; nj < 4; nj++) {
            const int cc = colBase + wc + nj * 8 + t4 * 2;
            const float bx = bo[cc], by = bo[cc + 1];
            #pragma unroll
            for (int half = 0; half < 2; half++) {
                const int r = rowBase + wr + mi * 16 + g + half * 8;
                float2 v;
                v.x = c[mi][nj][half * 2 + 0] + bx;
                v.y = c[mi][nj][half * 2 + 1] + by;
                *(float2*)&out[(size_t)r * HID + cc] = v;
            }
        }
    }
}

// ---------------------------------------------------------------- launch
extern "C" void kernel_launch(void* const* d_in, const int* in_sizes, int n_in,
                              void* d_out, int out_size)
{
    const float* X  = (const float*)d_in[0];
    const float* Wq = (const float*)d_in[1];
    const float* bq = (const float*)d_in[2];
    const float* Wk = (const float*)d_in[3];
    const float* bk = (const float*)d_in[4];
    const float* Wv = (const float*)d_in[5];
    const float* bv = (const float*)d_in[6];
    const float* Wo = (const float*)d_in[7];
    const float* bo = (const float*)d_in[8];
    float* out = (float*)d_out;

    // 1. transpose all weights into [N,K]
    {
        dim3 grid(32, 32, 4);
        transpose_kernel<<<grid, 256>>>(Wq, Wk, Wv, Wo);
    }
    // 2. QKV projections (tf32 mma.sync)
    {
        dim3 grid(HID / BN, MROWS / BM, 3);
        qkv_mma<<<grid, 256>>>(X, bq, bk, bv);
    }
    // 3. scores: K-resident bf16, colsum + fused exact diagonal -> g_diag
    {
        dim3 grid(LSEQ / 128, NHTOT);
        scores_mma<<<grid, 256>>>();
    }
    // 4. output projection with fused diag*V scaling
    {
        dim3 grid(HID / BN, MROWS / BM, 1);
        out_mma<<<grid, 256>>>(bo, out);
    }
}